// round 11
// baseline (speedup 1.0000x reference)
#include <cuda_runtime.h>
#include <math.h>

#define EPS 1e-8f

// Scratch for inter-chunk carries: [C][B][F] layout.
#define MAX_CARRY (1 << 23)
__device__ float g_carry[MAX_CARRY];

__device__ __forceinline__ float sqrt_approx(float x) {
    float r;
    asm("sqrt.approx.f32 %0, %1;" : "=f"(r) : "f"(x));
    return r;
}

// ---------------------------------------------------------------------------
// Phase 1: thread = (b, chunk k, f). Chunk's EMA contribution from state 0.
// F_C is compile-time so all strided offsets become LDG immediate offsets.
// ---------------------------------------------------------------------------
template <int F_C>
__global__ void __launch_bounds__(256)
phase1_t(const float* __restrict__ mag,
         const float* __restrict__ alpha,
         int B, int T, int C, int L)
{
    int tid = blockIdx.x * blockDim.x + threadIdx.x;
    int total = B * C * F_C;
    if (tid >= total) return;

    int f  = tid % F_C;
    int bk = tid / F_C;        // b*C + k
    int k  = bk % C;
    int b  = bk / C;

    int t0  = k * L;
    int len = T - t0; if (len > L) len = L;
    if (len <= 0) { g_carry[((size_t)k * B + b) * F_C + f] = 0.0f; return; }

    float a  = 1.0f / (1.0f + __expf(-alpha[f]));
    float om = 1.0f - a;

    const float* __restrict__ mp = mag + ((size_t)b * T + t0) * F_C + f;

    float s = 0.0f;
    int i = 0;
    int len8 = len & ~7;
    for (; i < len8; i += 8) {
        float m0 = mp[0 * F_C];
        float m1 = mp[1 * F_C];
        float m2 = mp[2 * F_C];
        float m3 = mp[3 * F_C];
        float m4 = mp[4 * F_C];
        float m5 = mp[5 * F_C];
        float m6 = mp[6 * F_C];
        float m7 = mp[7 * F_C];
        mp += 8 * F_C;
        s = fmaf(m0 * m0, a, s * om);
        s = fmaf(m1 * m1, a, s * om);
        s = fmaf(m2 * m2, a, s * om);
        s = fmaf(m3 * m3, a, s * om);
        s = fmaf(m4 * m4, a, s * om);
        s = fmaf(m5 * m5, a, s * om);
        s = fmaf(m6 * m6, a, s * om);
        s = fmaf(m7 * m7, a, s * om);
    }
    for (; i < len; i++) {
        float m = *mp; mp += F_C;
        s = fmaf(m * m, a, s * om);
    }

    g_carry[((size_t)k * B + b) * F_C + f] = s;
}

// ---------------------------------------------------------------------------
// Phase 2: thread = (b, chunk k, f). Reconstruct incoming state from carries,
// then emit outputs. Immediate-offset loads/stores via compile-time F_C.
// ---------------------------------------------------------------------------
template <int F_C>
__global__ void __launch_bounds__(256)
phase2_t(const float* __restrict__ mag,
         const float* __restrict__ s0,
         const float* __restrict__ weights,
         const float* __restrict__ bias,
         const float* __restrict__ alpha,
         float* __restrict__ out,
         int B, int T, int C, int L)
{
    int tid = blockIdx.x * blockDim.x + threadIdx.x;
    int total = B * C * F_C;
    if (tid >= total) return;

    int f  = tid % F_C;
    int bk = tid / F_C;
    int k  = bk % C;
    int b  = bk / C;

    int t0  = k * L;
    int len = T - t0; if (len > L) len = L;
    if (len <= 0) return;

    float a  = 1.0f / (1.0f + __expf(-alpha[f]));
    float om = 1.0f - a;
    float wf = weights[f];
    float bf = bias[f];

    // incoming state: s = s0; for j < k: s = s*om^L + c_j
    float s = s0[b * F_C + f];
    if (k > 0) {
        float omL = __powf(om, (float)L);
        const float* __restrict__ cp = g_carry + (size_t)b * F_C + f;
        for (int j = 0; j < k; j++) {
            s = fmaf(s, omL, cp[(size_t)j * B * F_C]);
        }
    }

    const float* __restrict__ mp = mag + ((size_t)b * T + t0) * F_C + f;
    float* __restrict__ op       = out + ((size_t)b * T + t0) * F_C + f;

    int i = 0;
    int len8 = len & ~7;
    for (; i < len8; i += 8) {
        float m0 = __ldcs(mp + 0 * F_C);
        float m1 = __ldcs(mp + 1 * F_C);
        float m2 = __ldcs(mp + 2 * F_C);
        float m3 = __ldcs(mp + 3 * F_C);
        float m4 = __ldcs(mp + 4 * F_C);
        float m5 = __ldcs(mp + 5 * F_C);
        float m6 = __ldcs(mp + 6 * F_C);
        float m7 = __ldcs(mp + 7 * F_C);
        mp += 8 * F_C;

        float o0, o1, o2, o3, o4, o5, o6, o7;
        s = fmaf(m0 * m0, a, s * om);
        o0 = __fdividef(m0, sqrt_approx(s) + EPS) * wf + bf;
        s = fmaf(m1 * m1, a, s * om);
        o1 = __fdividef(m1, sqrt_approx(s) + EPS) * wf + bf;
        s = fmaf(m2 * m2, a, s * om);
        o2 = __fdividef(m2, sqrt_approx(s) + EPS) * wf + bf;
        s = fmaf(m3 * m3, a, s * om);
        o3 = __fdividef(m3, sqrt_approx(s) + EPS) * wf + bf;
        s = fmaf(m4 * m4, a, s * om);
        o4 = __fdividef(m4, sqrt_approx(s) + EPS) * wf + bf;
        s = fmaf(m5 * m5, a, s * om);
        o5 = __fdividef(m5, sqrt_approx(s) + EPS) * wf + bf;
        s = fmaf(m6 * m6, a, s * om);
        o6 = __fdividef(m6, sqrt_approx(s) + EPS) * wf + bf;
        s = fmaf(m7 * m7, a, s * om);
        o7 = __fdividef(m7, sqrt_approx(s) + EPS) * wf + bf;

        __stcs(op + 0 * F_C, o0);
        __stcs(op + 1 * F_C, o1);
        __stcs(op + 2 * F_C, o2);
        __stcs(op + 3 * F_C, o3);
        __stcs(op + 4 * F_C, o4);
        __stcs(op + 5 * F_C, o5);
        __stcs(op + 6 * F_C, o6);
        __stcs(op + 7 * F_C, o7);
        op += 8 * F_C;
    }
    for (; i < len; i++) {
        float m = __ldcs(mp); mp += F_C;
        s = fmaf(m * m, a, s * om);
        __stcs(op, __fdividef(m, sqrt_approx(s) + EPS) * wf + bf);
        op += F_C;
    }
}

// ---------------------------------------------------------------------------
// Generic fallbacks (runtime F) — used only if the shape differs.
// ---------------------------------------------------------------------------
__global__ void __launch_bounds__(256)
phase1_g(const float* __restrict__ mag, const float* __restrict__ alpha,
         int B, int T, int F, int C, int L)
{
    int tid = blockIdx.x * blockDim.x + threadIdx.x;
    int total = B * C * F;
    if (tid >= total) return;
    int f = tid % F, bk = tid / F, k = bk % C, b = bk / C;
    int t0 = k * L;
    int len = T - t0; if (len > L) len = L;
    if (len <= 0) { g_carry[((size_t)k * B + b) * F + f] = 0.0f; return; }
    float a = 1.0f / (1.0f + __expf(-alpha[f]));
    float om = 1.0f - a;
    const float* mp = mag + ((size_t)b * T + t0) * F + f;
    float s = 0.0f;
    for (int i = 0; i < len; i++) { float m = *mp; mp += F; s = fmaf(m * m, a, s * om); }
    g_carry[((size_t)k * B + b) * F + f] = s;
}

__global__ void __launch_bounds__(256)
phase2_g(const float* __restrict__ mag, const float* __restrict__ s0,
         const float* __restrict__ weights, const float* __restrict__ bias,
         const float* __restrict__ alpha, float* __restrict__ out,
         int B, int T, int F, int C, int L)
{
    int tid = blockIdx.x * blockDim.x + threadIdx.x;
    int total = B * C * F;
    if (tid >= total) return;
    int f = tid % F, bk = tid / F, k = bk % C, b = bk / C;
    int t0 = k * L;
    int len = T - t0; if (len > L) len = L;
    if (len <= 0) return;
    float a = 1.0f / (1.0f + __expf(-alpha[f]));
    float om = 1.0f - a;
    float wf = weights[f], bf = bias[f];
    float s = s0[b * F + f];
    if (k > 0) {
        float omL = __powf(om, (float)L);
        const float* cp = g_carry + (size_t)b * F + f;
        for (int j = 0; j < k; j++) s = fmaf(s, omL, cp[(size_t)j * B * F]);
    }
    const float* mp = mag + ((size_t)b * T + t0) * F + f;
    float* op = out + ((size_t)b * T + t0) * F + f;
    for (int i = 0; i < len; i++) {
        float m = *mp; mp += F;
        s = fmaf(m * m, a, s * om);
        *op = __fdividef(m, sqrt_approx(s) + EPS) * wf + bf;
        op += F;
    }
}

extern "C" void kernel_launch(void* const* d_in, const int* in_sizes, int n_in,
                              void* d_out, int out_size)
{
    const float* mag     = (const float*)d_in[0];  // [B, T, F]
    const float* s0      = (const float*)d_in[1];  // [B, F]
    const float* weights = (const float*)d_in[2];  // [1, 1, F]
    const float* bias    = (const float*)d_in[3];  // [1, 1, F]
    const float* alpha   = (const float*)d_in[4];  // [1, F]
    float* out = (float*)d_out;

    int F  = in_sizes[4];
    int BF = in_sizes[1];
    int B  = BF / F;
    int T  = in_sizes[0] / BF;

    // Fixed chunk length L; every chunk except possibly the last has exactly
    // L steps (required by the om^L recombination).
    int L = (T + 31) / 32;         // target ~32 chunks
    if (L < 1) L = 1;
    int C = (T + L - 1) / L;
    while ((size_t)C * B * F > (size_t)MAX_CARRY && L < T) {
        L *= 2;
        C = (T + L - 1) / L;
    }

    int total   = B * C * F;
    int threads = 256;
    int blocks  = (total + threads - 1) / threads;

    if (F == 257) {
        phase1_t<257><<<blocks, threads>>>(mag, alpha, B, T, C, L);
        phase2_t<257><<<blocks, threads>>>(mag, s0, weights, bias, alpha, out,
                                           B, T, C, L);
    } else {
        phase1_g<<<blocks, threads>>>(mag, alpha, B, T, F, C, L);
        phase2_g<<<blocks, threads>>>(mag, s0, weights, bias, alpha, out,
                                      B, T, F, C, L);
    }
}